// round 13
// baseline (speedup 1.0000x reference)
#include <cuda_runtime.h>

// SSIM loss, fused separable 11x11 gaussian blur + ssim map + mean reduce.
// R13: R12's lean work profile (TW=64, 8-col P2 windows, 4-group P3) at
// high occupancy, by DELETING the raw s/d smem tiles: phase 2 loads 24-float
// aligned img windows straight from gmem (L1/L2-served) and computes s/d
// in registers. OOB fill = -1.0 in image space ((img+1)/2 -> 0, matching
// the reference's zero-padded conv input). smem 52KB -> 32KB -> 6 CTAs/SM
// (75% occ). P2 = two low-pressure passes (s-pair, d-pair; ~40 live regs).
// P3 uses float2 column pairs (52 LDS.64 vs 62 LDS.32). 2 syncs, not 3.

#define IMG      512
#define TW       64
#define TH       22
#define HALO     5
#define INH      32          // TH + 2*HALO  (P2 tasks = 32*8 = 256 = NT)
#define NT       256
#define HPLANE   (INH * TW)  // 2048 floats per blurred field

#define GX       8           // 512/64
#define GY       24          // 24*22 = 528 rows, tail masked
#define PL       96
#define NB       (GX * GY * PL)   // 18432 = 18*1024

#define SMEM_FLOATS (4 * HPLANE)         // 8192
#define SMEM_BYTES  (SMEM_FLOATS * 4)    // 32768

__device__ float g_part[NB];
__device__ float g_part2[18];

// 1D gaussian, sigma=1.5, K=11, normalized. Constant indices fold to
// FFMA immediates (rt_SMSP=1 imm-form).
__device__ __forceinline__ constexpr float gw(int k) {
    switch (k) {
        case 0:  return 0.00102838f;
        case 1:  return 0.00759877f;
        case 2:  return 0.03600077f;
        case 3:  return 0.10936069f;
        case 4:  return 0.21300554f;
        case 5:  return 0.26601173f;
        case 6:  return 0.21300554f;
        case 7:  return 0.10936069f;
        case 8:  return 0.03600077f;
        case 9:  return 0.00759877f;
        case 10: return 0.00102838f;
    }
    return 0.0f;
}

// One horizontal pass: build the 24-float s- or d-window straight from
// global memory, blur {v, v^2} for 8 output cols, store two planes.
// SUM=true -> v = (a+b)*0.5 + 1  (s-field); SUM=false -> v = (a-b)*0.5.
// OOB fill a=b=-1 makes both fields 0 at pad positions.
template <bool SUM>
__device__ __forceinline__ void hpass(const float* __restrict__ q1,
                                      const float* __restrict__ q2,
                                      bool rowok, int xb,
                                      float* __restrict__ d0,
                                      float* __restrict__ d1,
                                      int row, int c8) {
    float win[24];
    if (rowok && xb >= 0 && xb + 24 <= IMG) {
        const float4* a4 = (const float4*)(q1 + xb);
        const float4* b4 = (const float4*)(q2 + xb);
        #pragma unroll
        for (int t = 0; t < 6; t++) {
            float4 a = a4[t], b = b4[t];
            if (SUM) {
                win[4*t+0] = fmaf(a.x + b.x, 0.5f, 1.0f);
                win[4*t+1] = fmaf(a.y + b.y, 0.5f, 1.0f);
                win[4*t+2] = fmaf(a.z + b.z, 0.5f, 1.0f);
                win[4*t+3] = fmaf(a.w + b.w, 0.5f, 1.0f);
            } else {
                win[4*t+0] = (a.x - b.x) * 0.5f;
                win[4*t+1] = (a.y - b.y) * 0.5f;
                win[4*t+2] = (a.z - b.z) * 0.5f;
                win[4*t+3] = (a.w - b.w) * 0.5f;
            }
        }
    } else {
        #pragma unroll
        for (int t = 0; t < 24; t++) {
            int x = xb + t;
            bool ok = rowok && (x >= 0) && (x < IMG);
            float a = ok ? q1[x] : -1.0f;
            float b = ok ? q2[x] : -1.0f;
            win[t] = SUM ? fmaf(a + b, 0.5f, 1.0f) : (a - b) * 0.5f;
        }
    }

    float f[8]  = {0.f,0.f,0.f,0.f,0.f,0.f,0.f,0.f};
    float f2[8] = {0.f,0.f,0.f,0.f,0.f,0.f,0.f,0.f};
    #pragma unroll
    for (int i = 0; i < 18; i++) {
        float v  = win[i + 3];
        float vv = v * v;
        #pragma unroll
        for (int j = 0; j < 8; j++) {
            int k = i - j;
            if (k >= 0 && k < 11) {
                float w = gw(k);
                f[j]  = fmaf(v,  w, f[j]);
                f2[j] = fmaf(vv, w, f2[j]);
            }
        }
    }
    float* h0 = d0 + row * TW + c8;
    float* h1 = d1 + row * TW + c8;
    *(float4*)(h0 + 0) = make_float4(f[0],  f[1],  f[2],  f[3]);
    *(float4*)(h0 + 4) = make_float4(f[4],  f[5],  f[6],  f[7]);
    *(float4*)(h1 + 0) = make_float4(f2[0], f2[1], f2[2], f2[3]);
    *(float4*)(h1 + 4) = make_float4(f2[4], f2[5], f2[6], f2[7]);
}

__global__ __launch_bounds__(NT, 6)
void ssim_main(const float* __restrict__ img1, const float* __restrict__ img2) {
    extern __shared__ float smem[];
    float* sh = smem;                       // 4 planar fields [INH][TW]
    __shared__ float wsum[NT / 32];

    const int tid = threadIdx.x;
    const size_t pbase = (size_t)blockIdx.z * (IMG * IMG);
    const float* p1 = img1 + pbase;
    const float* p2 = img2 + pbase;

    // ---- Fused P1+P2: one (row, 8-col group) task per thread ----
    {
        const int row = tid >> 3;                       // 0..31
        const int c8  = (tid & 7) << 3;                 // 0,8,...,56
        const int gy  = blockIdx.y * TH - HALO + row;
        const bool rowok = (gy >= 0) && (gy < IMG);
        const int xb  = blockIdx.x * TW + c8 - 8;       // 32B-aligned
        const float* q1 = p1 + (ptrdiff_t)gy * IMG;
        const float* q2 = p2 + (ptrdiff_t)gy * IMG;

        hpass<true >(q1, q2, rowok, xb, sh + 0 * HPLANE, sh + 2 * HPLANE, row, c8);
        hpass<false>(q1, q2, rowok, xb, sh + 1 * HPLANE, sh + 3 * HPLANE, row, c8);
    }
    __syncthreads();

    // ---- Phase 3: vertical blur + ssim. 32 col-pairs x 8 row-groups
    //      (rows 3,3,3,3,3,3,2,2), float2 loads (conflict-free) ----
    const int cp = tid & 31;                 // column pair: cols {2cp, 2cp+1}
    const int g  = tid >> 5;                 // 0..7 (warp id)
    const int r_start = (g < 6) ? 3 * g : 18 + 2 * (g - 6);
    const int nrows   = (g < 6) ? 3 : 2;

    float2 a0[3], a1[3], a2[3], a3[3];
    #pragma unroll
    for (int j = 0; j < 3; j++) {
        a0[j] = make_float2(0.f, 0.f); a1[j] = make_float2(0.f, 0.f);
        a2[j] = make_float2(0.f, 0.f); a3[j] = make_float2(0.f, 0.f);
    }

    #pragma unroll
    for (int i = 0; i < 13; i++) {
        int ri = r_start + i;
        if (ri > INH - 1) ri = INH - 1;      // clamp feeds only masked outputs
        const float* hp = sh + ri * TW + 2 * cp;
        float2 h0 = *(const float2*)(hp + 0 * HPLANE);
        float2 h1 = *(const float2*)(hp + 1 * HPLANE);
        float2 h2 = *(const float2*)(hp + 2 * HPLANE);
        float2 h3 = *(const float2*)(hp + 3 * HPLANE);
        #pragma unroll
        for (int j = 0; j < 3; j++) {
            int k = i - j;
            if (k >= 0 && k < 11) {
                float w = gw(k);
                a0[j].x = fmaf(h0.x, w, a0[j].x); a0[j].y = fmaf(h0.y, w, a0[j].y);
                a1[j].x = fmaf(h1.x, w, a1[j].x); a1[j].y = fmaf(h1.y, w, a1[j].y);
                a2[j].x = fmaf(h2.x, w, a2[j].x); a2[j].y = fmaf(h2.y, w, a2[j].y);
                a3[j].x = fmaf(h3.x, w, a3[j].x); a3[j].y = fmaf(h3.y, w, a3[j].y);
            }
        }
    }

    const float C1 = 0.0001f;   // 0.01^2
    const float C2 = 0.0009f;   // 0.03^2
    const int   gyb = blockIdx.y * TH + r_start;
    float tsum = 0.f;
    #pragma unroll
    for (int j = 0; j < 3; j++) {
        bool valid = (j < nrows) && (gyb + j < IMG);
        if (valid) {
            #pragma unroll
            for (int c = 0; c < 2; c++) {
                float Bs  = c ? a0[j].y : a0[j].x;
                float Bd  = c ? a1[j].y : a1[j].x;
                float Bs2 = c ? a2[j].y : a2[j].x;
                float Bd2 = c ? a3[j].y : a3[j].x;
                float bss = Bs * Bs, bdd = Bd * Bd;
                float mu12   = 0.25f * (bss - bdd);        // mu1*mu2
                float musq   = 0.50f * (bss + bdd);        // mu1^2 + mu2^2
                float sig12  = 0.25f * (Bs2 - Bd2) - mu12; // sigma12
                float sigsum = 0.50f * (Bs2 + Bd2) - musq; // sig1^2+sig2^2
                float num = fmaf(2.f, mu12,  C1) * fmaf(2.f, sig12, C2);
                float den = (musq + C1) * (sigsum + C2);
                tsum += __fdividef(num, den);
            }
        }
    }

    // ---- Reduction: warp shuffle -> static wsum (1 barrier) -> STG ----
    #pragma unroll
    for (int off = 16; off; off >>= 1)
        tsum += __shfl_xor_sync(0xffffffffu, tsum, off);

    if ((tid & 31) == 0) wsum[tid >> 5] = tsum;
    __syncthreads();
    if (tid == 0) {
        float bs = 0.f;
        #pragma unroll
        for (int i = 0; i < NT / 32; i++) bs += wsum[i];
        int slot = (blockIdx.z * GY + blockIdx.y) * GX + blockIdx.x;
        g_part[slot] = bs;
    }
}

__global__ __launch_bounds__(1024)
void ssim_reduce1() {
    __shared__ float ws[32];
    const int tid = threadIdx.x;
    float s = g_part[blockIdx.x * 1024 + tid];

    #pragma unroll
    for (int off = 16; off; off >>= 1)
        s += __shfl_xor_sync(0xffffffffu, s, off);
    if ((tid & 31) == 0) ws[tid >> 5] = s;
    __syncthreads();
    if (tid < 32) {
        float t = ws[tid];
        #pragma unroll
        for (int off = 16; off; off >>= 1)
            t += __shfl_xor_sync(0xffffffffu, t, off);
        if (tid == 0) g_part2[blockIdx.x] = t;
    }
}

__global__ void ssim_fin(float* out, double inv_n) {
    const int tid = threadIdx.x;   // 32 threads
    double s = (tid < 18) ? (double)g_part2[tid] : 0.0;
    #pragma unroll
    for (int off = 16; off; off >>= 1)
        s += __shfl_xor_sync(0xffffffffu, s, off);
    if (tid == 0) out[0] = 1.0f - (float)(s * inv_n);
}

extern "C" void kernel_launch(void* const* d_in, const int* in_sizes, int n_in,
                              void* d_out, int out_size) {
    const float* img1 = (const float*)d_in[0];
    const float* img2 = (const float*)d_in[1];
    (void)n_in; (void)out_size; (void)in_sizes;

    cudaFuncSetAttribute(ssim_main, cudaFuncAttributeMaxDynamicSharedMemorySize,
                         SMEM_BYTES);

    dim3 grid(GX, GY, PL);
    ssim_main<<<grid, NT, SMEM_BYTES>>>(img1, img2);

    ssim_reduce1<<<18, 1024>>>();
    double inv_n = 1.0 / ((double)PL * IMG * IMG);
    ssim_fin<<<1, 32>>>((float*)d_out, inv_n);
}

// round 14
// speedup vs baseline: 1.4234x; 1.4234x over previous
#include <cuda_runtime.h>

// SSIM loss, fused separable 11x11 gaussian blur + ssim map + mean reduce.
// R14: R12's lean work profile (TW=64: -12% halo work/output; smem staging
// restored after R13's direct-gmem failure) at FULL occupancy via NT=512:
// smem 52KB limits CTAs to 4/SM, but 4 x 16 warps = 64 warps = 100% occ.
// P2 = 4-col windows (512 tasks = NT, balanced), s/d split passes keep
// peak live regs <= 32 (R11-proven); 2048 thr x 32 regs = exact RF fit.
// Invariant model: issue-work ~145us-eq; at issue ~78% -> ~185us main.

#define IMG      512
#define TW       64
#define TH       22
#define HALO     5
#define INW      74          // TW + 2*HALO
#define INWP     76          // padded row stride
#define INH      32          // TH + 2*HALO
#define NT       512
#define HPLANE   (INH * TW)  // 2048 floats per blurred field

#define GX       8           // 512/64
#define GY       24          // 24*22 = 528 rows, tail masked
#define PL       96
#define NB       (GX * GY * PL)   // 18432 = 18*1024

#define SMEM_FLOATS (2 * INH * INWP + 4 * HPLANE)   // 4864 + 8192 = 13056
#define SMEM_BYTES  (SMEM_FLOATS * 4)               // 52224

__device__ float g_part[NB];
__device__ float g_part2[18];

// 1D gaussian, sigma=1.5, K=11, normalized. Constant indices fold to
// FFMA immediates (rt_SMSP=1 imm-form).
__device__ __forceinline__ constexpr float gw(int k) {
    switch (k) {
        case 0:  return 0.00102838f;
        case 1:  return 0.00759877f;
        case 2:  return 0.03600077f;
        case 3:  return 0.10936069f;
        case 4:  return 0.21300554f;
        case 5:  return 0.26601173f;
        case 6:  return 0.21300554f;
        case 7:  return 0.10936069f;
        case 8:  return 0.03600077f;
        case 9:  return 0.00759877f;
        case 10: return 0.00102838f;
    }
    return 0.0f;
}

// One half of the horizontal blur: 16-float window -> {B(x), B(x^2)} for
// 4 cols, stored to planes d0, d1. Peak live ~24 regs.
__device__ __forceinline__ void hblur_half(const float* __restrict__ src,
                                           float* __restrict__ d0,
                                           float* __restrict__ d1,
                                           int row, int c0) {
    float a[16];
    {
        const float4* a4 = (const float4*)(src + row * INWP + c0);
        ((float4*)a)[0] = a4[0]; ((float4*)a)[1] = a4[1];
        ((float4*)a)[2] = a4[2]; ((float4*)a)[3] = a4[3];
    }
    float f[4]  = {0.f, 0.f, 0.f, 0.f};
    float f2[4] = {0.f, 0.f, 0.f, 0.f};
    #pragma unroll
    for (int i = 0; i < 14; i++) {
        float v = a[i];
        float vv = v * v;
        #pragma unroll
        for (int j = 0; j < 4; j++) {
            int k = i - j;
            if (k >= 0 && k < 11) {
                float w = gw(k);
                f[j]  = fmaf(v,  w, f[j]);
                f2[j] = fmaf(vv, w, f2[j]);
            }
        }
    }
    float* h0 = d0 + row * TW + c0;
    float* h1 = d1 + row * TW + c0;
    *(float4*)h0 = make_float4(f[0],  f[1],  f[2],  f[3]);
    *(float4*)h1 = make_float4(f2[0], f2[1], f2[2], f2[3]);
}

__global__ __launch_bounds__(NT, 4)
void ssim_main(const float* __restrict__ img1, const float* __restrict__ img2) {
    extern __shared__ float smem[];
    float* ss = smem;                       // s = x1+x2 tile [INH][INWP]
    float* sd = smem + INH * INWP;          // d = x1-x2 tile
    float* sh = smem + 2 * INH * INWP;      // 4 planar fields [INH][TW]
    __shared__ float wsum[NT / 32];

    const int tid = threadIdx.x;
    const int gx0 = blockIdx.x * TW - HALO;
    const int gy0 = blockIdx.y * TH - HALO;
    const size_t pbase = (size_t)blockIdx.z * (IMG * IMG);
    const float* p1 = img1 + pbase;
    const float* p2 = img2 + pbase;

    // ---- Phase 1: global -> smem. s=(i1+i2)*0.5+1, d=(i1-i2)*0.5.
    //      thread (r = tid>>4, c = tid&15) covers cols c+16k, 5 iters. ----
    {
        const int r  = tid >> 4;
        const int c  = tid & 15;
        const int gy = gy0 + r;
        const bool rowok = (gy >= 0) && (gy < IMG);
        const float* q1 = p1 + (ptrdiff_t)gy * IMG;
        const float* q2 = p2 + (ptrdiff_t)gy * IMG;
        #pragma unroll
        for (int k = 0; k < 5; k++) {
            int cc = c + 16 * k;
            if (k < 4 || cc < INWP) {
                int gx = gx0 + cc;
                float vs = 0.f, vd = 0.f;
                if (rowok && cc < INW && gx >= 0 && gx < IMG) {
                    float a = q1[gx], b = q2[gx];
                    vs = fmaf(a + b, 0.5f, 1.0f);
                    vd = (a - b) * 0.5f;
                }
                ss[r * INWP + cc] = vs;
                sd[r * INWP + cc] = vd;
            }
        }
    }
    __syncthreads();

    // ---- Phase 2: horizontal blur, 4 output cols/thread, 512 tasks ----
    {
        const int row = tid >> 4;           // 0..31
        const int c0  = (tid & 15) << 2;    // 0,4,...,60
        hblur_half(ss, sh + 0 * HPLANE, sh + 2 * HPLANE, row, c0);  // s half
        hblur_half(sd, sh + 1 * HPLANE, sh + 3 * HPLANE, row, c0);  // d half
    }
    __syncthreads();

    // ---- Phase 3: vertical blur + ssim. 64 cols x 8 groups
    //      (rows 3,3,3,3,3,3,2,2) ----
    const int col = tid & 63;
    const int g   = tid >> 6;               // 0..7
    const int r_start = (g < 6) ? 3 * g : 18 + 2 * (g - 6);
    const int nrows   = (g < 6) ? 3 : 2;

    float acc0[3], acc1[3], acc2[3], acc3[3];
    #pragma unroll
    for (int j = 0; j < 3; j++) {
        acc0[j] = 0.f; acc1[j] = 0.f; acc2[j] = 0.f; acc3[j] = 0.f;
    }

    #pragma unroll
    for (int i = 0; i < 13; i++) {
        int ri = r_start + i;
        if (ri > INH - 1) ri = INH - 1;      // clamp feeds only masked outputs
        const float* hp = sh + ri * TW + col;
        float h0 = hp[0 * HPLANE];
        float h1 = hp[1 * HPLANE];
        float h2 = hp[2 * HPLANE];
        float h3 = hp[3 * HPLANE];
        #pragma unroll
        for (int j = 0; j < 3; j++) {
            int k = i - j;
            if (k >= 0 && k < 11) {
                float w = gw(k);
                acc0[j] = fmaf(h0, w, acc0[j]);
                acc1[j] = fmaf(h1, w, acc1[j]);
                acc2[j] = fmaf(h2, w, acc2[j]);
                acc3[j] = fmaf(h3, w, acc3[j]);
            }
        }
    }

    const float C1 = 0.0001f;   // 0.01^2
    const float C2 = 0.0009f;   // 0.03^2
    const int   gyb = blockIdx.y * TH + r_start;
    float tsum = 0.f;
    #pragma unroll
    for (int j = 0; j < 3; j++) {
        bool valid = (j < nrows) && (gyb + j < IMG);
        if (valid) {
            float Bs  = acc0[j], Bd  = acc1[j];
            float Bs2 = acc2[j], Bd2 = acc3[j];
            float bss = Bs * Bs, bdd = Bd * Bd;
            float mu12   = 0.25f * (bss - bdd);        // mu1*mu2
            float musq   = 0.50f * (bss + bdd);        // mu1^2 + mu2^2
            float sig12  = 0.25f * (Bs2 - Bd2) - mu12; // sigma12
            float sigsum = 0.50f * (Bs2 + Bd2) - musq; // sig1^2 + sig2^2
            float num = fmaf(2.f, mu12,  C1) * fmaf(2.f, sig12, C2);
            float den = (musq + C1) * (sigsum + C2);
            tsum += __fdividef(num, den);
        }
    }

    // ---- Reduction: warp shuffle -> static wsum (1 barrier) -> STG ----
    #pragma unroll
    for (int off = 16; off; off >>= 1)
        tsum += __shfl_xor_sync(0xffffffffu, tsum, off);

    if ((tid & 31) == 0) wsum[tid >> 5] = tsum;
    __syncthreads();
    if (tid == 0) {
        float bs = 0.f;
        #pragma unroll
        for (int i = 0; i < NT / 32; i++) bs += wsum[i];
        int slot = (blockIdx.z * GY + blockIdx.y) * GX + blockIdx.x;
        g_part[slot] = bs;
    }
}

__global__ __launch_bounds__(1024)
void ssim_reduce1() {
    __shared__ float ws[32];
    const int tid = threadIdx.x;
    float s = g_part[blockIdx.x * 1024 + tid];

    #pragma unroll
    for (int off = 16; off; off >>= 1)
        s += __shfl_xor_sync(0xffffffffu, s, off);
    if ((tid & 31) == 0) ws[tid >> 5] = s;
    __syncthreads();
    if (tid < 32) {
        float t = ws[tid];
        #pragma unroll
        for (int off = 16; off; off >>= 1)
            t += __shfl_xor_sync(0xffffffffu, t, off);
        if (tid == 0) g_part2[blockIdx.x] = t;
    }
}

__global__ void ssim_fin(float* out, double inv_n) {
    const int tid = threadIdx.x;   // 32 threads
    double s = (tid < 18) ? (double)g_part2[tid] : 0.0;
    #pragma unroll
    for (int off = 16; off; off >>= 1)
        s += __shfl_xor_sync(0xffffffffu, s, off);
    if (tid == 0) out[0] = 1.0f - (float)(s * inv_n);
}

extern "C" void kernel_launch(void* const* d_in, const int* in_sizes, int n_in,
                              void* d_out, int out_size) {
    const float* img1 = (const float*)d_in[0];
    const float* img2 = (const float*)d_in[1];
    (void)n_in; (void)out_size; (void)in_sizes;

    cudaFuncSetAttribute(ssim_main, cudaFuncAttributeMaxDynamicSharedMemorySize,
                         SMEM_BYTES);

    dim3 grid(GX, GY, PL);
    ssim_main<<<grid, NT, SMEM_BYTES>>>(img1, img2);

    ssim_reduce1<<<18, 1024>>>();
    double inv_n = 1.0 / ((double)PL * IMG * IMG);
    ssim_fin<<<1, 32>>>((float*)d_out, inv_n);
}